// round 16
// baseline (speedup 1.0000x reference)
#include <cuda_runtime.h>
#include <cuda_fp16.h>
#include <cstdint>

// Problem constants
#define BATCH 4
#define SEQ   2048
#define CDIM  1024
#define HEADS 16
#define HD    64

// ---------------- scratch (device globals, fp16) ---------------------------
__device__ __half g_x16[(size_t)BATCH * SEQ * CDIM];
__device__ __half g_wa16[(size_t)3 * CDIM * CDIM];   // w_attn^T [3C, C]
__device__ __half g_wp16[(size_t)CDIM * CDIM];       // w_proj^T [C, C]
__device__ __half g_q[(size_t)BATCH * SEQ * CDIM];   // [B,H,T,D], pre-scaled
__device__ __half g_k[(size_t)BATCH * SEQ * CDIM];
__device__ __half g_v[(size_t)BATCH * SEQ * CDIM];
__device__ __half g_a[(size_t)BATCH * SEQ * CDIM];   // attention out [B*T, C]

// ---------------- helpers --------------------------------------------------
__device__ __forceinline__ uint32_t smem_u32(const void* p) {
    uint32_t a;
    asm("{ .reg .u64 t; cvta.to.shared.u64 t, %1; cvt.u32.u64 %0, t; }"
        : "=r"(a) : "l"(p));
    return a;
}
__device__ __forceinline__ void cp16(uint32_t dst, const void* src) {
    asm volatile("cp.async.cg.shared.global [%0], [%1], 16;"
                 :: "r"(dst), "l"(src) : "memory");
}
__device__ __forceinline__ void ldmatrix_x4(uint32_t* r, uint32_t addr) {
    asm volatile("ldmatrix.sync.aligned.m8n8.x4.shared.b16 {%0,%1,%2,%3}, [%4];"
                 : "=r"(r[0]), "=r"(r[1]), "=r"(r[2]), "=r"(r[3]) : "r"(addr));
}
__device__ __forceinline__ void ldmatrix_x4t(uint32_t* r, uint32_t addr) {
    asm volatile("ldmatrix.sync.aligned.m8n8.x4.trans.shared.b16 {%0,%1,%2,%3}, [%4];"
                 : "=r"(r[0]), "=r"(r[1]), "=r"(r[2]), "=r"(r[3]) : "r"(addr));
}
__device__ __forceinline__ void mma_f16(float* c, const uint32_t* a, const uint32_t* b) {
    asm volatile(
        "mma.sync.aligned.m16n8k16.row.col.f32.f16.f16.f32 "
        "{%0,%1,%2,%3}, {%4,%5,%6,%7}, {%8,%9}, {%0,%1,%2,%3};"
        : "+f"(c[0]), "+f"(c[1]), "+f"(c[2]), "+f"(c[3])
        : "r"(a[0]), "r"(a[1]), "r"(a[2]), "r"(a[3]), "r"(b[0]), "r"(b[1]));
}
__device__ __forceinline__ float exp2a(float x) {
    float r;
    asm("ex2.approx.ftz.f32 %0, %1;" : "=f"(r) : "f"(x));
    return r;
}
__device__ __forceinline__ uint32_t packh2(float a, float b) {
    __half2 t = __floats2half2_rn(a, b);
    return *(uint32_t*)&t;
}

// ---------------- fused prep: x convert + both weight transposes -----------
#define NXB  8192                  // (4*2048*1024/4) / 256
#define NWA  (96 * 32)
#define NWP  (32 * 32)

__global__ __launch_bounds__(256) void prep_kernel(
    const float* __restrict__ x, const float* __restrict__ wa,
    const float* __restrict__ wp, __half* __restrict__ x16,
    __half* __restrict__ wa16, __half* __restrict__ wp16)
{
    const int bid = blockIdx.x;
    const int tid = threadIdx.x;
    if (bid < NXB) {
        int i = bid * 256 + tid;
        float4 v = ((const float4*)x)[i];
        ushort4 o;
        o.x = __half_as_ushort(__float2half_rn(v.x));
        o.y = __half_as_ushort(__float2half_rn(v.y));
        o.z = __half_as_ushort(__float2half_rn(v.z));
        o.w = __half_as_ushort(__float2half_rn(v.w));
        ((ushort4*)x16)[i] = o;
        return;
    }
    __shared__ float tile[32][33];
    const float* w;  __half* t16;  int N, tb;
    if (bid < NXB + NWA) { w = wa; t16 = wa16; N = 3 * CDIM; tb = bid - NXB; }
    else                 { w = wp; t16 = wp16; N = CDIM;     tb = bid - NXB - NWA; }
    const int ncols = N / 32;
    const int n0 = (tb % ncols) * 32, k0 = (tb / ncols) * 32;
    const int tx = tid & 31, ty = tid >> 5;
    #pragma unroll
    for (int r = 0; r < 32; r += 8)
        tile[ty + r][tx] = w[(size_t)(k0 + ty + r) * N + n0 + tx];
    __syncthreads();
    #pragma unroll
    for (int r = 0; r < 32; r += 8)
        t16[(size_t)(n0 + ty + r) * CDIM + k0 + tx] = __float2half_rn(tile[tx][ty + r]);
}

// -- fp16 GEMM: 128x128 CTA, 256 thr (8 warps x 64x32), BK=64, 3-stage ------
#define GBM 128
#define GBN 128
#define GBK 64
#define ROWB 144
#define TILE_BYTES (128 * ROWB)           // 18432
#define STAGE_BYTES (2 * TILE_BYTES)      // 36864: A16, B16
#define GEMM_SMEM (3 * STAGE_BYTES)       // 110592/CTA -> 2 CTAs/SM

__device__ __forceinline__ void load_stage(
    uint32_t sbase, const char* const* gsrc, int K, int s, int kblk, int tid)
{
    const uint32_t stage = sbase + s * STAGE_BYTES;
    #pragma unroll
    for (int j = 0; j < 8; j++) {
        const int c = tid + j * 256;
        const int t = c >> 10;             // constant per j
        const int rr = (c & 1023) >> 3;
        const int q = c & 7;
        cp16(stage + t * TILE_BYTES + rr * ROWB + q * 16,
             gsrc[t] + (size_t)kblk * 128 + (size_t)rr * (K * 2) + q * 16);
    }
}

// MODE 0: C = A@B^T + bias (fp32).  MODE 1: QKV epilogue -> head-major fp16.
template <int MODE>
__global__ __launch_bounds__(256, 2) void gemm_mma_kernel(
    const __half* __restrict__ A, const __half* __restrict__ B,
    const float* __restrict__ bias, float* __restrict__ C,
    __half* __restrict__ q16, __half* __restrict__ k16, __half* __restrict__ v16,
    int Ntot, int K)
{
    extern __shared__ char smem[];
    const uint32_t sbase = smem_u32(smem);
    const int tid = threadIdx.x;
    const int wid = tid >> 5, lane = tid & 31;
    const int m0 = blockIdx.y * GBM, n0 = blockIdx.x * GBN;
    const int wm = (wid >> 2) * 64;
    const int wn = (wid & 3) * 32;

    const char* gsrc[2] = {
        (const char*)(A + (size_t)m0 * K),
        (const char*)(B + (size_t)n0 * K) };

    float acc[4][4][4];
    #pragma unroll
    for (int i = 0; i < 4; i++)
        #pragma unroll
        for (int j = 0; j < 4; j++)
            #pragma unroll
            for (int p = 0; p < 4; p++) acc[i][j][p] = 0.f;

    const uint32_t a_row_off = (wm + (lane & 15)) * ROWB + (lane >> 4) * 16;
    // B: k32-spanning x4 (attention-proven pattern): rows lane&7, chunk lane>>3
    const uint32_t b_off = TILE_BYTES + (wn + (lane & 7)) * ROWB + (lane >> 3) * 16;

    const int NITER = K / GBK;   // 16

    load_stage(sbase, gsrc, K, 0, 0, tid);
    asm volatile("cp.async.commit_group;" ::: "memory");
    load_stage(sbase, gsrc, K, 1, 1, tid);
    asm volatile("cp.async.commit_group;" ::: "memory");

    int cur = 0, nxt2 = 2;
    for (int it = 0; it < NITER; it++) {
        asm volatile("cp.async.wait_group 1;" ::: "memory");
        __syncthreads();
        if (it + 2 < NITER)
            load_stage(sbase, gsrc, K, nxt2, it + 2, tid);
        asm volatile("cp.async.commit_group;" ::: "memory");

        const uint32_t st = sbase + cur * STAGE_BYTES;

        #pragma unroll
        for (int hf = 0; hf < 2; hf++) {       // two k32 halves of BK=64
            // B fragments for whole k32: one x4 per nt, contiguous pairs
            uint32_t bq[4][4];
            #pragma unroll
            for (int nt = 0; nt < 4; nt++)
                ldmatrix_x4(bq[nt], st + b_off + nt * 8 * ROWB + hf * 64);
            #pragma unroll
            for (int ks = 0; ks < 2; ks++) {   // k16 steps within half
                const uint32_t koff = hf * 64 + ks * 32;
                uint32_t af[4][4];
                #pragma unroll
                for (int mt = 0; mt < 4; mt++)
                    ldmatrix_x4(af[mt], st + a_row_off + mt * 16 * ROWB + koff);
                #pragma unroll
                for (int nt = 0; nt < 4; nt++) {
                    uint32_t bb[2] = { bq[nt][ks * 2], bq[nt][ks * 2 + 1] };
                    #pragma unroll
                    for (int mt = 0; mt < 4; mt++)
                        mma_f16(acc[mt][nt], af[mt], bb);
                }
            }
        }
        cur = (cur == 2) ? 0 : cur + 1;
        nxt2 = (nxt2 == 2) ? 0 : nxt2 + 1;
    }

    const int crow = lane >> 2;
    const int ccol = (lane & 3) * 2;

    if (MODE == 0) {
        #pragma unroll
        for (int nt = 0; nt < 4; nt++) {
            const int n = n0 + wn + nt * 8 + ccol;
            const float2 bb = *(const float2*)(bias + n);
            #pragma unroll
            for (int mt = 0; mt < 4; mt++) {
                const int m = m0 + wm + mt * 16 + crow;
                float2 v0 = { acc[mt][nt][0] + bb.x, acc[mt][nt][1] + bb.y };
                float2 v1 = { acc[mt][nt][2] + bb.x, acc[mt][nt][3] + bb.y };
                *(float2*)(C + (size_t)m * Ntot + n) = v0;
                *(float2*)(C + (size_t)(m + 8) * Ntot + n) = v1;
            }
        }
    } else {
        const int comp = n0 >> 10;
        const float fs = (comp == 0) ? 0.18033688011112042f : 1.0f; // 0.125*log2(e)
        __half* oh = (comp == 0) ? q16 : (comp == 1) ? k16 : v16;
        #pragma unroll
        for (int nt = 0; nt < 4; nt++) {
            const int coltile = wn + nt * 8 + ccol;
            const int colg = (n0 & 1023) + coltile;
            const int hh = colg >> 6, d = colg & 63;
            const float2 bb = *(const float2*)(bias + n0 + coltile);
            #pragma unroll
            for (int mt = 0; mt < 4; mt++) {
                const int m = m0 + wm + mt * 16 + crow;
                const int b = m >> 11, t = m & 2047;
                #pragma unroll
                for (int half = 0; half < 2; half++) {
                    const int tt = t + half * 8;
                    float v0 = (acc[mt][nt][half * 2 + 0] + bb.x) * fs;
                    float v1 = (acc[mt][nt][half * 2 + 1] + bb.y) * fs;
                    size_t ro = (((size_t)b * HEADS + hh) * SEQ + tt) * HD + d;
                    *(__half2*)(oh + ro) = __floats2half2_rn(v0, v1);
                }
            }
        }
    }
}

// ---------------- flash attention, fp16 (128-row kv stages) -----------------
#define ARS 144
#define ATQ (128 * ARS)           // 18432
#define AT64 (64 * ARS)           // 9216
#define KV_STAGE (2 * 128 * ARS)  // 36864: K(128 rows), V(128 rows)
#define ATT_SMEM (ATQ + 2 * KV_STAGE)   // 92160/CTA -> 2 CTAs/SM

__device__ __forceinline__ void attn_load_kv128(
    uint32_t sbase, int stage, size_t bh_off, int bt, int tid,
    const __half* k16, const __half* v16)
{
    const __half* srcs[2] = { k16, v16 };
    const uint32_t sb = sbase + ATQ + stage * KV_STAGE;
    #pragma unroll
    for (int t = 0; t < 2; t++) {
        const char* base = (const char*)(srcs[t] + bh_off + (size_t)bt * 128 * HD);
        #pragma unroll
        for (int j = 0; j < 4; j++) {
            int c = tid + j * 256;
            int r = c >> 3, q = c & 7;
            cp16(sb + t * 128 * ARS + r * ARS + q * 16, base + r * 128 + q * 16);
        }
    }
}

__global__ __launch_bounds__(256) void attn_mma_kernel(
    const __half* __restrict__ q16, const __half* __restrict__ k16,
    const __half* __restrict__ v16, __half* __restrict__ o16)
{
    extern __shared__ char smem[];
    const uint32_t sbase = smem_u32(smem);
    const int qt = gridDim.x - 1 - blockIdx.x;   // heavy-first
    const int h = blockIdx.y, b = blockIdx.z;
    const int tid = threadIdx.x;
    const int wid = tid >> 5, lane = tid & 31;
    const int wm = wid * 16;

    const size_t bh_off = ((size_t)b * HEADS + h) * SEQ * HD;

    // --- load Q tile ---
    {
        const char* base = (const char*)(q16 + bh_off + (size_t)qt * 128 * HD);
        #pragma unroll
        for (int j = 0; j < 4; j++) {
            int c = tid + j * 256;
            int r = c >> 3, q = c & 7;
            cp16(sbase + r * ARS + q * 16, base + r * 128 + q * 16);
        }
        asm volatile("cp.async.commit_group;" ::: "memory");
    }
    attn_load_kv128(sbase, 0, bh_off, 0, tid, k16, v16);
    asm volatile("cp.async.commit_group;" ::: "memory");

    const uint32_t a_off = (wm + (lane & 15)) * ARS + (lane >> 4) * 16;
    const uint32_t b_off = (lane & 7) * ARS + (lane >> 3) * 16;
    const uint32_t v_off = (lane & 15) * ARS + (lane >> 4) * 16;

    uint32_t qf[4][4];
    float of[8][4];
    #pragma unroll
    for (int nt = 0; nt < 8; nt++)
        #pragma unroll
        for (int p = 0; p < 4; p++) of[nt][p] = 0.f;
    float m0 = -1e30f, m1 = -1e30f, l0 = 0.f, l1 = 0.f;

    const int NT = qt + 1;
    const int Rw = qt * 128 + wm;

    for (int bt = 0; bt < NT; bt++) {
        const int cur = bt & 1;
        if (bt + 1 < NT) {
            attn_load_kv128(sbase, cur ^ 1, bh_off, bt + 1, tid, k16, v16);
            asm volatile("cp.async.commit_group;" ::: "memory");
            asm volatile("cp.async.wait_group 1;" ::: "memory");
        } else {
            asm volatile("cp.async.wait_group 0;" ::: "memory");
        }
        __syncthreads();

        if (bt == 0) {
            #pragma unroll
            for (int ks = 0; ks < 4; ks++)
                ldmatrix_x4(qf[ks], sbase + a_off + ks * 32);
        }

        const uint32_t stg = sbase + ATQ + cur * KV_STAGE;

        #pragma unroll
        for (int sub = 0; sub < 2; sub++) {
            const int Cb = bt * 128 + sub * 64;
            if (Cb > Rw + 15) continue;
            const uint32_t sK = stg + sub * AT64;
            const uint32_t sV = stg + 128 * ARS + sub * AT64;

            // ---- S = Q @ K^T ----
            float sf[8][4];
            #pragma unroll
            for (int nt = 0; nt < 8; nt++)
                #pragma unroll
                for (int p = 0; p < 4; p++) sf[nt][p] = 0.f;

            #pragma unroll
            for (int nt = 0; nt < 8; nt++) {
                uint32_t k0[4], k1[4];
                ldmatrix_x4(k0, sK + nt * 8 * ARS + b_off);
                ldmatrix_x4(k1, sK + nt * 8 * ARS + b_off + 64);
                #pragma unroll
                for (int ks = 0; ks < 4; ks++) {
                    const int sub2 = (ks & 1) * 2;
                    const uint32_t* kp = (ks < 2) ? k0 : k1;
                    uint32_t bb[2] = { kp[sub2], kp[sub2 + 1] };
                    mma_f16(sf[nt], qf[ks], bb);
                }
            }

            // ---- causal mask (partial tiles only) ----
            if (Cb + 63 > Rw) {
                const int r0g = Rw + (lane >> 2);
                const int cbb = Cb + (lane & 3) * 2;
                #pragma unroll
                for (int nt = 0; nt < 8; nt++) {
                    const int c0 = cbb + nt * 8;
                    if (c0 > r0g)     sf[nt][0] = -1e30f;
                    if (c0 + 1 > r0g) sf[nt][1] = -1e30f;
                    if (c0 > r0g + 8)     sf[nt][2] = -1e30f;
                    if (c0 + 1 > r0g + 8) sf[nt][3] = -1e30f;
                }
            }

            // ---- online softmax ----
            float mx0 = -1e30f, mx1 = -1e30f;
            #pragma unroll
            for (int nt = 0; nt < 8; nt++) {
                mx0 = fmaxf(mx0, fmaxf(sf[nt][0], sf[nt][1]));
                mx1 = fmaxf(mx1, fmaxf(sf[nt][2], sf[nt][3]));
            }
            mx0 = fmaxf(mx0, __shfl_xor_sync(0xffffffffu, mx0, 1));
            mx0 = fmaxf(mx0, __shfl_xor_sync(0xffffffffu, mx0, 2));
            mx1 = fmaxf(mx1, __shfl_xor_sync(0xffffffffu, mx1, 1));
            mx1 = fmaxf(mx1, __shfl_xor_sync(0xffffffffu, mx1, 2));
            const float mn0 = fmaxf(m0, mx0), mn1 = fmaxf(m1, mx1);
            const float al0 = exp2a(m0 - mn0), al1 = exp2a(m1 - mn1);
            float s0 = 0.f, s1 = 0.f;
            #pragma unroll
            for (int nt = 0; nt < 8; nt++) {
                sf[nt][0] = exp2a(sf[nt][0] - mn0); s0 += sf[nt][0];
                sf[nt][1] = exp2a(sf[nt][1] - mn0); s0 += sf[nt][1];
                sf[nt][2] = exp2a(sf[nt][2] - mn1); s1 += sf[nt][2];
                sf[nt][3] = exp2a(sf[nt][3] - mn1); s1 += sf[nt][3];
            }
            s0 += __shfl_xor_sync(0xffffffffu, s0, 1);
            s0 += __shfl_xor_sync(0xffffffffu, s0, 2);
            s1 += __shfl_xor_sync(0xffffffffu, s1, 1);
            s1 += __shfl_xor_sync(0xffffffffu, s1, 2);
            l0 = l0 * al0 + s0; l1 = l1 * al1 + s1;
            m0 = mn0; m1 = mn1;
            #pragma unroll
            for (int nt = 0; nt < 8; nt++) {
                of[nt][0] *= al0; of[nt][1] *= al0;
                of[nt][2] *= al1; of[nt][3] *= al1;
            }

            // ---- O += P @ V ----
            #pragma unroll
            for (int s = 0; s < 4; s++) {
                uint32_t pa[4];
                pa[0] = packh2(sf[2*s][0],   sf[2*s][1]);
                pa[1] = packh2(sf[2*s][2],   sf[2*s][3]);
                pa[2] = packh2(sf[2*s+1][0], sf[2*s+1][1]);
                pa[3] = packh2(sf[2*s+1][2], sf[2*s+1][3]);
                #pragma unroll
                for (int ntp = 0; ntp < 4; ntp++) {
                    uint32_t vf[4];
                    ldmatrix_x4t(vf, sV + s * 16 * ARS + v_off + ntp * 32);
                    uint32_t b0[2] = { vf[0], vf[1] }, b1[2] = { vf[2], vf[3] };
                    mma_f16(of[2*ntp],   pa, b0);
                    mma_f16(of[2*ntp+1], pa, b1);
                }
            }
        }
        __syncthreads();
    }

    // ---- epilogue: normalize, fp16 store [B*T, C] ----
    const float inv0 = 1.f / l0, inv1 = 1.f / l1;
    const int r0 = Rw + (lane >> 2);
    const size_t rowbase0 = ((size_t)b * SEQ + r0) * CDIM + h * HD;
    const size_t rowbase1 = rowbase0 + 8 * CDIM;
    const int cb = (lane & 3) * 2;
    #pragma unroll
    for (int nt = 0; nt < 8; nt++) {
        const int d = nt * 8 + cb;
        *(__half2*)(o16 + rowbase0 + d) =
            __floats2half2_rn(of[nt][0] * inv0, of[nt][1] * inv0);
        *(__half2*)(o16 + rowbase1 + d) =
            __floats2half2_rn(of[nt][2] * inv1, of[nt][3] * inv1);
    }
}

// ---------------------------------------------------------------------------
extern "C" void kernel_launch(void* const* d_in, const int* in_sizes, int n_in,
                              void* d_out, int out_size)
{
    const float* x      = (const float*)d_in[0];
    const float* w_attn = (const float*)d_in[1];
    const float* b_attn = (const float*)d_in[2];
    const float* w_proj = (const float*)d_in[3];
    const float* b_proj = (const float*)d_in[4];
    float* out = (float*)d_out;

    __half *x16, *wa16, *wp16, *q16, *k16, *v16, *a16;
    cudaGetSymbolAddress((void**)&x16, g_x16);
    cudaGetSymbolAddress((void**)&wa16, g_wa16);
    cudaGetSymbolAddress((void**)&wp16, g_wp16);
    cudaGetSymbolAddress((void**)&q16, g_q);
    cudaGetSymbolAddress((void**)&k16, g_k);
    cudaGetSymbolAddress((void**)&v16, g_v);
    cudaGetSymbolAddress((void**)&a16, g_a);

    const int M = BATCH * SEQ;

    cudaFuncSetAttribute(gemm_mma_kernel<0>, cudaFuncAttributeMaxDynamicSharedMemorySize, GEMM_SMEM);
    cudaFuncSetAttribute(gemm_mma_kernel<1>, cudaFuncAttributeMaxDynamicSharedMemorySize, GEMM_SMEM);
    cudaFuncSetAttribute(attn_mma_kernel, cudaFuncAttributeMaxDynamicSharedMemorySize, ATT_SMEM);

    // 1) fused prep
    prep_kernel<<<NXB + NWA + NWP, 256>>>(x, w_attn, w_proj, x16, wa16, wp16);

    // 2) QKV GEMM -> head-major fp16 q/k/v
    {
        dim3 grid(3 * CDIM / GBN, M / GBM);   // (24, 64)
        gemm_mma_kernel<1><<<grid, 256, GEMM_SMEM>>>(
            x16, wa16, b_attn, nullptr, q16, k16, v16, 3 * CDIM, CDIM);
    }
    // 3) flash attention
    {
        dim3 grid(SEQ / 128, HEADS, BATCH);
        attn_mma_kernel<<<grid, 256, ATT_SMEM>>>(q16, k16, v16, a16);
    }
    // 4) projection GEMM
    {
        dim3 grid(CDIM / GBN, M / GBM);       // (8, 64)
        gemm_mma_kernel<0><<<grid, 256, GEMM_SMEM>>>(
            a16, wp16, b_proj, out, nullptr, nullptr, nullptr, CDIM, CDIM);
    }
}

// round 17
// speedup vs baseline: 1.0479x; 1.0479x over previous
#include <cuda_runtime.h>
#include <cuda_fp16.h>
#include <cstdint>

// Problem constants
#define BATCH 4
#define SEQ   2048
#define CDIM  1024
#define HEADS 16
#define HD    64

// ---------------- scratch (device globals, fp16) ---------------------------
__device__ __half g_x16[(size_t)BATCH * SEQ * CDIM];
__device__ __half g_wa16[(size_t)3 * CDIM * CDIM];   // w_attn^T [3C, C]
__device__ __half g_wp16[(size_t)CDIM * CDIM];       // w_proj^T [C, C]
__device__ __half g_q[(size_t)BATCH * SEQ * CDIM];   // [B,H,T,D], pre-scaled
__device__ __half g_k[(size_t)BATCH * SEQ * CDIM];
__device__ __half g_v[(size_t)BATCH * SEQ * CDIM];
__device__ __half g_a[(size_t)BATCH * SEQ * CDIM];   // attention out [B*T, C]

// ---------------- helpers --------------------------------------------------
__device__ __forceinline__ uint32_t smem_u32(const void* p) {
    uint32_t a;
    asm("{ .reg .u64 t; cvta.to.shared.u64 t, %1; cvt.u32.u64 %0, t; }"
        : "=r"(a) : "l"(p));
    return a;
}
__device__ __forceinline__ void cp16(uint32_t dst, const void* src) {
    asm volatile("cp.async.cg.shared.global [%0], [%1], 16;"
                 :: "r"(dst), "l"(src) : "memory");
}
__device__ __forceinline__ void ldmatrix_x4(uint32_t* r, uint32_t addr) {
    asm volatile("ldmatrix.sync.aligned.m8n8.x4.shared.b16 {%0,%1,%2,%3}, [%4];"
                 : "=r"(r[0]), "=r"(r[1]), "=r"(r[2]), "=r"(r[3]) : "r"(addr));
}
__device__ __forceinline__ void ldmatrix_x2(uint32_t* r, uint32_t addr) {
    asm volatile("ldmatrix.sync.aligned.m8n8.x2.shared.b16 {%0,%1}, [%2];"
                 : "=r"(r[0]), "=r"(r[1]) : "r"(addr));
}
__device__ __forceinline__ void ldmatrix_x4t(uint32_t* r, uint32_t addr) {
    asm volatile("ldmatrix.sync.aligned.m8n8.x4.trans.shared.b16 {%0,%1,%2,%3}, [%4];"
                 : "=r"(r[0]), "=r"(r[1]), "=r"(r[2]), "=r"(r[3]) : "r"(addr));
}
__device__ __forceinline__ void mma_f16(float* c, const uint32_t* a, const uint32_t* b) {
    asm volatile(
        "mma.sync.aligned.m16n8k16.row.col.f32.f16.f16.f32 "
        "{%0,%1,%2,%3}, {%4,%5,%6,%7}, {%8,%9}, {%0,%1,%2,%3};"
        : "+f"(c[0]), "+f"(c[1]), "+f"(c[2]), "+f"(c[3])
        : "r"(a[0]), "r"(a[1]), "r"(a[2]), "r"(a[3]), "r"(b[0]), "r"(b[1]));
}
__device__ __forceinline__ float exp2a(float x) {
    float r;
    asm("ex2.approx.ftz.f32 %0, %1;" : "=f"(r) : "f"(x));
    return r;
}
__device__ __forceinline__ uint32_t packh2(float a, float b) {
    __half2 t = __floats2half2_rn(a, b);
    return *(uint32_t*)&t;
}

// ---------------- fused prep: x convert + both weight transposes -----------
#define NXB  8192                  // (4*2048*1024/4) / 256
#define NWA  (96 * 32)
#define NWP  (32 * 32)

__global__ __launch_bounds__(256) void prep_kernel(
    const float* __restrict__ x, const float* __restrict__ wa,
    const float* __restrict__ wp, __half* __restrict__ x16,
    __half* __restrict__ wa16, __half* __restrict__ wp16)
{
    const int bid = blockIdx.x;
    const int tid = threadIdx.x;
    if (bid < NXB) {
        int i = bid * 256 + tid;
        float4 v = ((const float4*)x)[i];
        ushort4 o;
        o.x = __half_as_ushort(__float2half_rn(v.x));
        o.y = __half_as_ushort(__float2half_rn(v.y));
        o.z = __half_as_ushort(__float2half_rn(v.z));
        o.w = __half_as_ushort(__float2half_rn(v.w));
        ((ushort4*)x16)[i] = o;
        return;
    }
    __shared__ float tile[32][33];
    const float* w;  __half* t16;  int N, tb;
    if (bid < NXB + NWA) { w = wa; t16 = wa16; N = 3 * CDIM; tb = bid - NXB; }
    else                 { w = wp; t16 = wp16; N = CDIM;     tb = bid - NXB - NWA; }
    const int ncols = N / 32;
    const int n0 = (tb % ncols) * 32, k0 = (tb / ncols) * 32;
    const int tx = tid & 31, ty = tid >> 5;
    #pragma unroll
    for (int r = 0; r < 32; r += 8)
        tile[ty + r][tx] = w[(size_t)(k0 + ty + r) * N + n0 + tx];
    __syncthreads();
    #pragma unroll
    for (int r = 0; r < 32; r += 8)
        t16[(size_t)(n0 + ty + r) * CDIM + k0 + tx] = __float2half_rn(tile[tx][ty + r]);
}

// -- fp16 GEMM: 128x128 CTA, 256 thr (8 warps x 64x32), BK=64, 3-stage ------
#define GBM 128
#define GBN 128
#define GBK 64
#define ROWB 144
#define TILE_BYTES (128 * ROWB)           // 18432
#define STAGE_BYTES (2 * TILE_BYTES)      // 36864: A16, B16
#define GEMM_SMEM (3 * STAGE_BYTES)       // 110592/CTA -> 2 CTAs/SM

// half = 0 -> A chunks (j 0..3), half = 1 -> B chunks (j 4..7)
__device__ __forceinline__ void load_half(
    uint32_t sbase, const char* const* gsrc, int K, int s, int kblk, int tid, int half)
{
    const uint32_t stage = sbase + s * STAGE_BYTES;
    #pragma unroll
    for (int jj = 0; jj < 4; jj++) {
        const int j = half * 4 + jj;
        const int c = tid + j * 256;
        const int t = c >> 10;             // constant per j
        const int rr = (c & 1023) >> 3;
        const int q = c & 7;
        cp16(stage + t * TILE_BYTES + rr * ROWB + q * 16,
             gsrc[t] + (size_t)kblk * 128 + (size_t)rr * (K * 2) + q * 16);
    }
}

// MODE 0: C = A@B^T + bias (fp32).  MODE 1: QKV epilogue -> head-major fp16.
template <int MODE>
__global__ __launch_bounds__(256, 2) void gemm_mma_kernel(
    const __half* __restrict__ A, const __half* __restrict__ B,
    const float* __restrict__ bias, float* __restrict__ C,
    __half* __restrict__ q16, __half* __restrict__ k16, __half* __restrict__ v16,
    int Ntot, int K)
{
    extern __shared__ char smem[];
    const uint32_t sbase = smem_u32(smem);
    const int tid = threadIdx.x;
    const int wid = tid >> 5, lane = tid & 31;
    const int m0 = blockIdx.y * GBM, n0 = blockIdx.x * GBN;
    const int wm = (wid >> 2) * 64;
    const int wn = (wid & 3) * 32;

    const char* gsrc[2] = {
        (const char*)(A + (size_t)m0 * K),
        (const char*)(B + (size_t)n0 * K) };

    float acc[4][4][4];
    #pragma unroll
    for (int i = 0; i < 4; i++)
        #pragma unroll
        for (int j = 0; j < 4; j++)
            #pragma unroll
            for (int p = 0; p < 4; p++) acc[i][j][p] = 0.f;

    const uint32_t a_row_off = (wm + (lane & 15)) * ROWB + (lane >> 4) * 16;
    const uint32_t b_row_off = TILE_BYTES + (wn + (lane & 7)) * ROWB
                             + ((lane >> 3) & 1) * 16;

    const int NITER = K / GBK;   // 16

    load_half(sbase, gsrc, K, 0, 0, tid, 0);
    load_half(sbase, gsrc, K, 0, 0, tid, 1);
    asm volatile("cp.async.commit_group;" ::: "memory");
    load_half(sbase, gsrc, K, 1, 1, tid, 0);
    load_half(sbase, gsrc, K, 1, 1, tid, 1);
    asm volatile("cp.async.commit_group;" ::: "memory");

    int cur = 0, nxt2 = 2;
    for (int it = 0; it < NITER; it++) {
        asm volatile("cp.async.wait_group 1;" ::: "memory");
        __syncthreads();

        const uint32_t st = sbase + cur * STAGE_BYTES;
        const bool pf = (it + 2 < NITER);

        #pragma unroll
        for (int hf = 0; hf < 2; hf++) {       // two k32 halves of BK=64
            // spread prefetch issue: A before hf0 compute, B before hf1
            if (pf) load_half(sbase, gsrc, K, nxt2, it + 2, tid, hf);
            if (hf == 1)
                asm volatile("cp.async.commit_group;" ::: "memory");

            #pragma unroll
            for (int ks = 0; ks < 2; ks++) {   // k16 steps within half
                const uint32_t koff = hf * 64 + ks * 32;
                uint32_t af[4][4];
                #pragma unroll
                for (int mt = 0; mt < 4; mt++)
                    ldmatrix_x4(af[mt], st + a_row_off + mt * 16 * ROWB + koff);
                uint32_t bf[4][2];
                #pragma unroll
                for (int nt = 0; nt < 4; nt++)
                    ldmatrix_x2(bf[nt], st + b_row_off + nt * 8 * ROWB + koff);
                #pragma unroll
                for (int nt = 0; nt < 4; nt++)
                    #pragma unroll
                    for (int mt = 0; mt < 4; mt++)
                        mma_f16(acc[mt][nt], af[mt], bf[nt]);
            }
        }
        cur = (cur == 2) ? 0 : cur + 1;
        nxt2 = (nxt2 == 2) ? 0 : nxt2 + 1;
    }

    const int crow = lane >> 2;
    const int ccol = (lane & 3) * 2;

    if (MODE == 0) {
        #pragma unroll
        for (int nt = 0; nt < 4; nt++) {
            const int n = n0 + wn + nt * 8 + ccol;
            const float2 bb = *(const float2*)(bias + n);
            #pragma unroll
            for (int mt = 0; mt < 4; mt++) {
                const int m = m0 + wm + mt * 16 + crow;
                float2 v0 = { acc[mt][nt][0] + bb.x, acc[mt][nt][1] + bb.y };
                float2 v1 = { acc[mt][nt][2] + bb.x, acc[mt][nt][3] + bb.y };
                *(float2*)(C + (size_t)m * Ntot + n) = v0;
                *(float2*)(C + (size_t)(m + 8) * Ntot + n) = v1;
            }
        }
    } else {
        const int comp = n0 >> 10;
        const float fs = (comp == 0) ? 0.18033688011112042f : 1.0f; // 0.125*log2(e)
        __half* oh = (comp == 0) ? q16 : (comp == 1) ? k16 : v16;
        #pragma unroll
        for (int nt = 0; nt < 4; nt++) {
            const int coltile = wn + nt * 8 + ccol;
            const int colg = (n0 & 1023) + coltile;
            const int hh = colg >> 6, d = colg & 63;
            const float2 bb = *(const float2*)(bias + n0 + coltile);
            #pragma unroll
            for (int mt = 0; mt < 4; mt++) {
                const int m = m0 + wm + mt * 16 + crow;
                const int b = m >> 11, t = m & 2047;
                #pragma unroll
                for (int half = 0; half < 2; half++) {
                    const int tt = t + half * 8;
                    float v0 = (acc[mt][nt][half * 2 + 0] + bb.x) * fs;
                    float v1 = (acc[mt][nt][half * 2 + 1] + bb.y) * fs;
                    size_t ro = (((size_t)b * HEADS + hh) * SEQ + tt) * HD + d;
                    *(__half2*)(oh + ro) = __floats2half2_rn(v0, v1);
                }
            }
        }
    }
}

// ---------------- flash attention, fp16 (128-row kv stages) -----------------
#define ARS 144
#define ATQ (128 * ARS)           // 18432
#define AT64 (64 * ARS)           // 9216
#define KV_STAGE (2 * 128 * ARS)  // 36864: K(128 rows), V(128 rows)
#define ATT_SMEM (ATQ + 2 * KV_STAGE)   // 92160/CTA -> 2 CTAs/SM

__device__ __forceinline__ void attn_load_kv128(
    uint32_t sbase, int stage, size_t bh_off, int bt, int tid,
    const __half* k16, const __half* v16)
{
    const __half* srcs[2] = { k16, v16 };
    const uint32_t sb = sbase + ATQ + stage * KV_STAGE;
    #pragma unroll
    for (int t = 0; t < 2; t++) {
        const char* base = (const char*)(srcs[t] + bh_off + (size_t)bt * 128 * HD);
        #pragma unroll
        for (int j = 0; j < 4; j++) {
            int c = tid + j * 256;
            int r = c >> 3, q = c & 7;
            cp16(sb + t * 128 * ARS + r * ARS + q * 16, base + r * 128 + q * 16);
        }
    }
}

__global__ __launch_bounds__(256) void attn_mma_kernel(
    const __half* __restrict__ q16, const __half* __restrict__ k16,
    const __half* __restrict__ v16, __half* __restrict__ o16)
{
    extern __shared__ char smem[];
    const uint32_t sbase = smem_u32(smem);
    const int qt = gridDim.x - 1 - blockIdx.x;   // heavy-first
    const int h = blockIdx.y, b = blockIdx.z;
    const int tid = threadIdx.x;
    const int wid = tid >> 5, lane = tid & 31;
    const int wm = wid * 16;

    const size_t bh_off = ((size_t)b * HEADS + h) * SEQ * HD;

    // --- load Q tile ---
    {
        const char* base = (const char*)(q16 + bh_off + (size_t)qt * 128 * HD);
        #pragma unroll
        for (int j = 0; j < 4; j++) {
            int c = tid + j * 256;
            int r = c >> 3, q = c & 7;
            cp16(sbase + r * ARS + q * 16, base + r * 128 + q * 16);
        }
        asm volatile("cp.async.commit_group;" ::: "memory");
    }
    attn_load_kv128(sbase, 0, bh_off, 0, tid, k16, v16);
    asm volatile("cp.async.commit_group;" ::: "memory");

    const uint32_t a_off = (wm + (lane & 15)) * ARS + (lane >> 4) * 16;
    const uint32_t b_off = (lane & 7) * ARS + (lane >> 3) * 16;
    const uint32_t v_off = (lane & 15) * ARS + (lane >> 4) * 16;

    uint32_t qf[4][4];
    float of[8][4];
    #pragma unroll
    for (int nt = 0; nt < 8; nt++)
        #pragma unroll
        for (int p = 0; p < 4; p++) of[nt][p] = 0.f;
    float m0 = -1e30f, m1 = -1e30f, l0 = 0.f, l1 = 0.f;

    const int NT = qt + 1;
    const int Rw = qt * 128 + wm;

    for (int bt = 0; bt < NT; bt++) {
        const int cur = bt & 1;
        if (bt + 1 < NT) {
            attn_load_kv128(sbase, cur ^ 1, bh_off, bt + 1, tid, k16, v16);
            asm volatile("cp.async.commit_group;" ::: "memory");
            asm volatile("cp.async.wait_group 1;" ::: "memory");
        } else {
            asm volatile("cp.async.wait_group 0;" ::: "memory");
        }
        __syncthreads();

        if (bt == 0) {
            #pragma unroll
            for (int ks = 0; ks < 4; ks++)
                ldmatrix_x4(qf[ks], sbase + a_off + ks * 32);
        }

        const uint32_t stg = sbase + ATQ + cur * KV_STAGE;

        #pragma unroll
        for (int sub = 0; sub < 2; sub++) {
            const int Cb = bt * 128 + sub * 64;
            if (Cb > Rw + 15) continue;
            const uint32_t sK = stg + sub * AT64;
            const uint32_t sV = stg + 128 * ARS + sub * AT64;

            // ---- S = Q @ K^T ----
            float sf[8][4];
            #pragma unroll
            for (int nt = 0; nt < 8; nt++)
                #pragma unroll
                for (int p = 0; p < 4; p++) sf[nt][p] = 0.f;

            #pragma unroll
            for (int nt = 0; nt < 8; nt++) {
                uint32_t k0[4], k1[4];
                ldmatrix_x4(k0, sK + nt * 8 * ARS + b_off);
                ldmatrix_x4(k1, sK + nt * 8 * ARS + b_off + 64);
                #pragma unroll
                for (int ks = 0; ks < 4; ks++) {
                    const int sub2 = (ks & 1) * 2;
                    const uint32_t* kp = (ks < 2) ? k0 : k1;
                    uint32_t bb[2] = { kp[sub2], kp[sub2 + 1] };
                    mma_f16(sf[nt], qf[ks], bb);
                }
            }

            // ---- causal mask (partial tiles only) ----
            if (Cb + 63 > Rw) {
                const int r0g = Rw + (lane >> 2);
                const int cbb = Cb + (lane & 3) * 2;
                #pragma unroll
                for (int nt = 0; nt < 8; nt++) {
                    const int c0 = cbb + nt * 8;
                    if (c0 > r0g)     sf[nt][0] = -1e30f;
                    if (c0 + 1 > r0g) sf[nt][1] = -1e30f;
                    if (c0 > r0g + 8)     sf[nt][2] = -1e30f;
                    if (c0 + 1 > r0g + 8) sf[nt][3] = -1e30f;
                }
            }

            // ---- online softmax ----
            float mx0 = -1e30f, mx1 = -1e30f;
            #pragma unroll
            for (int nt = 0; nt < 8; nt++) {
                mx0 = fmaxf(mx0, fmaxf(sf[nt][0], sf[nt][1]));
                mx1 = fmaxf(mx1, fmaxf(sf[nt][2], sf[nt][3]));
            }
            mx0 = fmaxf(mx0, __shfl_xor_sync(0xffffffffu, mx0, 1));
            mx0 = fmaxf(mx0, __shfl_xor_sync(0xffffffffu, mx0, 2));
            mx1 = fmaxf(mx1, __shfl_xor_sync(0xffffffffu, mx1, 1));
            mx1 = fmaxf(mx1, __shfl_xor_sync(0xffffffffu, mx1, 2));
            const float mn0 = fmaxf(m0, mx0), mn1 = fmaxf(m1, mx1);
            const float al0 = exp2a(m0 - mn0), al1 = exp2a(m1 - mn1);
            float s0 = 0.f, s1 = 0.f;
            #pragma unroll
            for (int nt = 0; nt < 8; nt++) {
                sf[nt][0] = exp2a(sf[nt][0] - mn0); s0 += sf[nt][0];
                sf[nt][1] = exp2a(sf[nt][1] - mn0); s0 += sf[nt][1];
                sf[nt][2] = exp2a(sf[nt][2] - mn1); s1 += sf[nt][2];
                sf[nt][3] = exp2a(sf[nt][3] - mn1); s1 += sf[nt][3];
            }
            s0 += __shfl_xor_sync(0xffffffffu, s0, 1);
            s0 += __shfl_xor_sync(0xffffffffu, s0, 2);
            s1 += __shfl_xor_sync(0xffffffffu, s1, 1);
            s1 += __shfl_xor_sync(0xffffffffu, s1, 2);
            l0 = l0 * al0 + s0; l1 = l1 * al1 + s1;
            m0 = mn0; m1 = mn1;
            #pragma unroll
            for (int nt = 0; nt < 8; nt++) {
                of[nt][0] *= al0; of[nt][1] *= al0;
                of[nt][2] *= al1; of[nt][3] *= al1;
            }

            // ---- O += P @ V ----
            #pragma unroll
            for (int s = 0; s < 4; s++) {
                uint32_t pa[4];
                pa[0] = packh2(sf[2*s][0],   sf[2*s][1]);
                pa[1] = packh2(sf[2*s][2],   sf[2*s][3]);
                pa[2] = packh2(sf[2*s+1][0], sf[2*s+1][1]);
                pa[3] = packh2(sf[2*s+1][2], sf[2*s+1][3]);
                #pragma unroll
                for (int ntp = 0; ntp < 4; ntp++) {
                    uint32_t vf[4];
                    ldmatrix_x4t(vf, sV + s * 16 * ARS + v_off + ntp * 32);
                    uint32_t b0[2] = { vf[0], vf[1] }, b1[2] = { vf[2], vf[3] };
                    mma_f16(of[2*ntp],   pa, b0);
                    mma_f16(of[2*ntp+1], pa, b1);
                }
            }
        }
        __syncthreads();
    }

    // ---- epilogue: normalize, fp16 store [B*T, C] ----
    const float inv0 = 1.f / l0, inv1 = 1.f / l1;
    const int r0 = Rw + (lane >> 2);
    const size_t rowbase0 = ((size_t)b * SEQ + r0) * CDIM + h * HD;
    const size_t rowbase1 = rowbase0 + 8 * CDIM;
    const int cb = (lane & 3) * 2;
    #pragma unroll
    for (int nt = 0; nt < 8; nt++) {
        const int d = nt * 8 + cb;
        *(__half2*)(o16 + rowbase0 + d) =
            __floats2half2_rn(of[nt][0] * inv0, of[nt][1] * inv0);
        *(__half2*)(o16 + rowbase1 + d) =
            __floats2half2_rn(of[nt][2] * inv1, of[nt][3] * inv1);
    }
}

// ---------------------------------------------------------------------------
extern "C" void kernel_launch(void* const* d_in, const int* in_sizes, int n_in,
                              void* d_out, int out_size)
{
    const float* x      = (const float*)d_in[0];
    const float* w_attn = (const float*)d_in[1];
    const float* b_attn = (const float*)d_in[2];
    const float* w_proj = (const float*)d_in[3];
    const float* b_proj = (const float*)d_in[4];
    float* out = (float*)d_out;

    __half *x16, *wa16, *wp16, *q16, *k16, *v16, *a16;
    cudaGetSymbolAddress((void**)&x16, g_x16);
    cudaGetSymbolAddress((void**)&wa16, g_wa16);
    cudaGetSymbolAddress((void**)&wp16, g_wp16);
    cudaGetSymbolAddress((void**)&q16, g_q);
    cudaGetSymbolAddress((void**)&k16, g_k);
    cudaGetSymbolAddress((void**)&v16, g_v);
    cudaGetSymbolAddress((void**)&a16, g_a);

    const int M = BATCH * SEQ;

    cudaFuncSetAttribute(gemm_mma_kernel<0>, cudaFuncAttributeMaxDynamicSharedMemorySize, GEMM_SMEM);
    cudaFuncSetAttribute(gemm_mma_kernel<1>, cudaFuncAttributeMaxDynamicSharedMemorySize, GEMM_SMEM);
    cudaFuncSetAttribute(attn_mma_kernel, cudaFuncAttributeMaxDynamicSharedMemorySize, ATT_SMEM);

    // 1) fused prep
    prep_kernel<<<NXB + NWA + NWP, 256>>>(x, w_attn, w_proj, x16, wa16, wp16);

    // 2) QKV GEMM -> head-major fp16 q/k/v
    {
        dim3 grid(3 * CDIM / GBN, M / GBM);   // (24, 64)
        gemm_mma_kernel<1><<<grid, 256, GEMM_SMEM>>>(
            x16, wa16, b_attn, nullptr, q16, k16, v16, 3 * CDIM, CDIM);
    }
    // 3) flash attention
    {
        dim3 grid(SEQ / 128, HEADS, BATCH);
        attn_mma_kernel<<<grid, 256, ATT_SMEM>>>(q16, k16, v16, a16);
    }
    // 4) projection GEMM
    {
        dim3 grid(CDIM / GBN, M / GBM);       // (8, 64)
        gemm_mma_kernel<0><<<grid, 256, GEMM_SMEM>>>(
            a16, wp16, b_proj, out, nullptr, nullptr, nullptr, CDIM, CDIM);
    }
}